// round 3
// baseline (speedup 1.0000x reference)
#include <cuda_runtime.h>
#include <cuda_bf16.h>

#define NVV 4096
#define NHH 1024
#define TT  64
#define BBB 32
#define TBB 2048   // T*B

// ---------------- scratch (static device globals; no allocation) -----------
__device__ float g_WV[NHH * TBB];   // W @ V            [NH, T*B]
__device__ float g_HB[NHH * TBB];   // hid_bias         [NH, T*B]
__device__ float g_H1[NHH * TBB];   // first h sample   [NH, T*B]
__device__ float g_P [NVV * TBB];   // W^T @ H1         [NV, T*B]
__device__ float g_VM[NVV * TBB];   // vm sample        [NV, T*B]
__device__ float g_Q [NHH * TBB];   // W @ VM           [NH, T*B]
__device__ float g_R [NVV * TBB];   // W^T @ H2         [NV, T*B]

// ---------------- threefry2x32 (JAX-compatible) -----------------------------
__host__ __device__ __forceinline__ unsigned int rotl32(unsigned int v, int d) {
    return (v << d) | (v >> (32 - d));
}

__host__ __device__ inline void tf2x32(unsigned int k0, unsigned int k1,
                                       unsigned int x0, unsigned int x1,
                                       unsigned int &o0, unsigned int &o1)
{
    unsigned int ks2 = k0 ^ k1 ^ 0x1BD11BDAu;
    x0 += k0; x1 += k1;
#define TF_R(r) { x0 += x1; x1 = rotl32(x1, (r)); x1 ^= x0; }
    TF_R(13) TF_R(15) TF_R(26) TF_R(6)
    x0 += k1;  x1 += ks2 + 1u;
    TF_R(17) TF_R(29) TF_R(16) TF_R(24)
    x0 += ks2; x1 += k0 + 2u;
    TF_R(13) TF_R(15) TF_R(26) TF_R(6)
    x0 += k0;  x1 += k1 + 3u;
    TF_R(17) TF_R(29) TF_R(16) TF_R(24)
    x0 += k1;  x1 += ks2 + 4u;
    TF_R(13) TF_R(15) TF_R(26) TF_R(6)
    x0 += ks2; x1 += k0 + 5u;
#undef TF_R
    o0 = x0; o1 = x1;
}

struct Keys64 { unsigned int a[TT]; unsigned int b[TT]; };

__device__ __forceinline__ float u01(unsigned int bits) {
    return __uint_as_float((bits >> 9) | 0x3f800000u) - 1.0f;
}
__device__ __forceinline__ float sigmoidf_(float x) {
    return 1.0f / (1.0f + expf(-x));
}

// ---------------- tiled fp32 SGEMM ------------------------------------------
// C[M,N] = A * B.  TA=false: A row-major [M,K]. TA=true: use A^T where A is
// stored row-major [K,M].  B row-major [K,N].  All dims multiples of tiles.
#define GBM 128
#define GBN 64
#define GBK 16

template<bool TA>
__global__ void __launch_bounds__(256)
sgemm(const float* __restrict__ A, const float* __restrict__ B,
      float* __restrict__ C, int M, int N, int K)
{
    __shared__ float As[GBK][GBM + 4];
    __shared__ float Bs[GBK][GBN];

    const int tid = threadIdx.x;
    const int m0 = blockIdx.y * GBM;
    const int n0 = blockIdx.x * GBN;

    float acc[8][4];
#pragma unroll
    for (int i = 0; i < 8; i++)
#pragma unroll
        for (int j = 0; j < 4; j++) acc[i][j] = 0.0f;

    const int tr = tid >> 4;   // 0..15 -> 8 rows each
    const int tc = tid & 15;   // 0..15 -> 4 cols each

    for (int k0 = 0; k0 < K; k0 += GBK) {
        if (!TA) {
            const int kk = tid & 15, mb = tid >> 4;
#pragma unroll
            for (int j = 0; j < 8; j++) {
                int mm = mb + j * 16;
                As[kk][mm] = A[(long)(m0 + mm) * K + (k0 + kk)];
            }
        } else {
            const int mm = tid & 127, kb = tid >> 7;
#pragma unroll
            for (int j = 0; j < 8; j++) {
                int kk = kb + j * 2;
                As[kk][mm] = A[(long)(k0 + kk) * M + (m0 + mm)];
            }
        }
        {
            const int nn = tid & 63, kb = tid >> 6;
#pragma unroll
            for (int j = 0; j < 4; j++) {
                int kk = kb + j * 4;
                Bs[kk][nn] = B[(long)(k0 + kk) * N + (n0 + nn)];
            }
        }
        __syncthreads();

#pragma unroll
        for (int kk = 0; kk < GBK; kk++) {
            float av[8], bv[4];
#pragma unroll
            for (int i = 0; i < 8; i++) av[i] = As[kk][tr * 8 + i];
#pragma unroll
            for (int j = 0; j < 4; j++) bv[j] = Bs[kk][tc * 4 + j];
#pragma unroll
            for (int i = 0; i < 8; i++)
#pragma unroll
                for (int j = 0; j < 4; j++) acc[i][j] += av[i] * bv[j];
        }
        __syncthreads();
    }

#pragma unroll
    for (int i = 0; i < 8; i++)
#pragma unroll
        for (int j = 0; j < 4; j++)
            C[(long)(m0 + tr * 8 + i) * N + (n0 + tc * 4 + j)] = acc[i][j];
}

// ---------------- recurrence step: hid_bias_t, r_t --------------------------
// r_t = sigmoid(WV[:,t,:] + U @ r_{t-1} + b_h)   (b_init at t=0)
__global__ void __launch_bounds__(256)
recur_step(const float* __restrict__ U, const float* __restrict__ b_h,
           const float* __restrict__ b_init, const float* __restrict__ WV,
           float* __restrict__ rt, float* __restrict__ hb, int t)
{
    int tidx = blockIdx.x * blockDim.x + threadIdx.x;   // 0..32767
    int i = tidx >> 5;
    int b = tidx & 31;

    float acc;
    if (t == 0) {
        acc = b_init[i];
    } else {
        acc = b_h[i];
        const float* __restrict__ Urow = U + (long)i * NHH;
        const float* __restrict__ rcol = rt + (long)(t - 1) * BBB + b;
        float s0 = 0.f, s1 = 0.f, s2 = 0.f, s3 = 0.f;
#pragma unroll 4
        for (int j = 0; j < NHH; j += 4) {
            s0 += Urow[j + 0] * rcol[(long)(j + 0) * TBB];
            s1 += Urow[j + 1] * rcol[(long)(j + 1) * TBB];
            s2 += Urow[j + 2] * rcol[(long)(j + 2) * TBB];
            s3 += Urow[j + 3] * rcol[(long)(j + 3) * TBB];
        }
        acc += ((s0 + s1) + (s2 + s3));
    }
    long idx = (long)i * TBB + (long)t * BBB + b;
    hb[idx] = acc;
    rt[idx] = sigmoidf_(acc + WV[idx]);
}

// ---------------- bernoulli sampling ----------------------------------------
// JAX threefry_partitionable=True (modern default):
//   random_bits(key, 32, shape) at flat index n -> threefry2x32(key, (0, n)),
//   output word = bits1 ^ bits2.  One thread per element; coalesced.
__global__ void __launch_bounds__(256)
sample_kernel(const float* __restrict__ pre,
              const float* __restrict__ rowbias,   // b_v or nullptr
              const float* __restrict__ fullbias,  // hid_bias or nullptr
              float* __restrict__ outbuf,
              Keys64 keys, int N, int preIsProb)
{
    const int t = blockIdx.y;
    const int n = blockIdx.x * blockDim.x + threadIdx.x;  // 0 .. N*B-1

    unsigned int b1, b2;
    tf2x32(keys.a[t], keys.b[t], 0u, (unsigned int)n, b1, b2);
    float uu = u01(b1 ^ b2);

    const int i = n >> 5;           // row within [N,B] slice (B=32)
    const int b = n & 31;
    const long idx = (long)i * TBB + (long)t * BBB + b;

    float p;
    if (preIsProb) {
        p = pre[idx];
    } else {
        float x = pre[idx];
        if (rowbias)  x += rowbias[i];
        if (fullbias) x += fullbias[idx];
        p = sigmoidf_(x);
    }
    outbuf[idx] = (uu < p) ? 1.0f : 0.0f;
}

// ---------------- host ------------------------------------------------------
extern "C" void kernel_launch(void* const* d_in, const int* in_sizes, int n_in,
                              void* d_out, int out_size)
{
    const float* v      = (const float*)d_in[0];  // [NV, T, B]
    const float* W      = (const float*)d_in[1];  // [NH, NV]
    const float* U      = (const float*)d_in[2];  // [NH, NH]
    const float* b_v    = (const float*)d_in[3];  // [NV]
    const float* b_h    = (const float*)d_in[4];  // [NH]
    const float* b_init = (const float*)d_in[5];  // [NH]

    float* out    = (float*)d_out;
    float* vmodel = out;                                   // [NV, T, B]
    float* rmodel = out + (long)NVV * TBB;                 // [NH, T, B]
    float* rt     = out + (long)(NVV + NHH) * TBB;         // [NH, T, B]

    float *WV, *HB, *H1, *P, *VM, *Q, *R;
    cudaGetSymbolAddress((void**)&WV, g_WV);
    cudaGetSymbolAddress((void**)&HB, g_HB);
    cudaGetSymbolAddress((void**)&H1, g_H1);
    cudaGetSymbolAddress((void**)&P,  g_P);
    cudaGetSymbolAddress((void**)&VM, g_VM);
    cudaGetSymbolAddress((void**)&Q,  g_Q);
    cudaGetSymbolAddress((void**)&R,  g_R);

    // ---- JAX key schedule, threefry_partitionable=True (modern default) ----
    // key(42) -> data (0, 42)
    // split(key, n)[i] = threefry2x32(key, (0, i)); child key = (o0, o1)
    // k0, ks = split(key); keys_t = split(ks, 63);
    // per-t: subkeys = split(key_t, 4) -> [h1, vm, h2, v_model]
    unsigned int tk0[TT], tk1[TT];
    unsigned int ksa, ksb;
    tf2x32(0u, 42u, 0u, 0u, tk0[0], tk1[0]);   // k0
    tf2x32(0u, 42u, 0u, 1u, ksa, ksb);         // ks
    for (int t = 1; t < TT; t++)
        tf2x32(ksa, ksb, 0u, (unsigned int)(t - 1), tk0[t], tk1[t]);

    Keys64 KH1, KVM, KH2, KVX;
    for (int t = 0; t < TT; t++) {
        tf2x32(tk0[t], tk1[t], 0u, 0u, KH1.a[t], KH1.b[t]);
        tf2x32(tk0[t], tk1[t], 0u, 1u, KVM.a[t], KVM.b[t]);
        tf2x32(tk0[t], tk1[t], 0u, 2u, KH2.a[t], KH2.b[t]);
        tf2x32(tk0[t], tk1[t], 0u, 3u, KVX.a[t], KVX.b[t]);
    }

    // ---- pipeline -----------------------------------------------------------
    // 1) WV = W @ V        [1024 x 2048], K=4096
    sgemm<false><<<dim3(TBB / GBN, NHH / GBM), 256>>>(W, v, WV, NHH, TBB, NVV);

    // 2) sequential recurrence over t: hid_bias + rt
    for (int t = 0; t < TT; t++)
        recur_step<<<(NHH * BBB) / 256, 256>>>(U, b_h, b_init, WV, rt, HB, t);

    // 3) h1 = bern(rt)
    sample_kernel<<<dim3((NHH * BBB) / 256, TT), 256>>>(
        rt, nullptr, nullptr, H1, KH1, NHH, 1);

    // 4) P = W^T @ H1      [4096 x 2048], K=1024
    sgemm<true><<<dim3(TBB / GBN, NVV / GBM), 256>>>(W, H1, P, NVV, TBB, NHH);

    // 5) vm = bern(sigmoid(P + b_v))
    sample_kernel<<<dim3((NVV * BBB) / 256, TT), 256>>>(
        P, b_v, nullptr, VM, KVM, NVV, 0);

    // 6) Q = W @ VM        [1024 x 2048], K=4096
    sgemm<false><<<dim3(TBB / GBN, NHH / GBM), 256>>>(W, VM, Q, NHH, TBB, NVV);

    // 7) h2 = bern(sigmoid(Q + hid_bias))  -> r_model output (also H2 input)
    sample_kernel<<<dim3((NHH * BBB) / 256, TT), 256>>>(
        Q, nullptr, HB, rmodel, KH2, NHH, 0);

    // 8) R = W^T @ H2      [4096 x 2048], K=1024
    sgemm<true><<<dim3(TBB / GBN, NVV / GBM), 256>>>(W, rmodel, R, NVV, TBB, NHH);

    // 9) v_model = bern(sigmoid(R + b_v))
    sample_kernel<<<dim3((NVV * BBB) / 256, TT), 256>>>(
        R, b_v, nullptr, vmodel, KVX, NVV, 0);

    (void)in_sizes; (void)n_in; (void)out_size;
}

// round 5
// speedup vs baseline: 1.8063x; 1.8063x over previous
#include <cuda_runtime.h>
#include <cuda_bf16.h>

#define NVV 4096
#define NHH 1024
#define TT  64
#define BBB 32
#define TBB 2048   // T*B

// ---------------- scratch (static device globals; no allocation) -----------
__device__ float g_WV[NHH * TBB];   // W @ V            [NH, T*B]
__device__ float g_HB[NHH * TBB];   // hid_bias         [NH, T*B]
__device__ float g_H1[NHH * TBB];   // first h sample   [NH, T*B]
__device__ float g_P [NVV * TBB];   // W^T @ H1         [NV, T*B]
__device__ float g_VM[NVV * TBB];   // vm sample        [NV, T*B]
__device__ float g_Q [NHH * TBB];   // W @ VM           [NH, T*B]
__device__ float g_R [NVV * TBB];   // W^T @ H2         [NV, T*B]

// ---------------- threefry2x32 (JAX-compatible) -----------------------------
__host__ __device__ __forceinline__ unsigned int rotl32(unsigned int v, int d) {
    return (v << d) | (v >> (32 - d));
}

__host__ __device__ inline void tf2x32(unsigned int k0, unsigned int k1,
                                       unsigned int x0, unsigned int x1,
                                       unsigned int &o0, unsigned int &o1)
{
    unsigned int ks2 = k0 ^ k1 ^ 0x1BD11BDAu;
    x0 += k0; x1 += k1;
#define TF_R(r) { x0 += x1; x1 = rotl32(x1, (r)); x1 ^= x0; }
    TF_R(13) TF_R(15) TF_R(26) TF_R(6)
    x0 += k1;  x1 += ks2 + 1u;
    TF_R(17) TF_R(29) TF_R(16) TF_R(24)
    x0 += ks2; x1 += k0 + 2u;
    TF_R(13) TF_R(15) TF_R(26) TF_R(6)
    x0 += k0;  x1 += k1 + 3u;
    TF_R(17) TF_R(29) TF_R(16) TF_R(24)
    x0 += k1;  x1 += ks2 + 4u;
    TF_R(13) TF_R(15) TF_R(26) TF_R(6)
    x0 += ks2; x1 += k0 + 5u;
#undef TF_R
    o0 = x0; o1 = x1;
}

struct Keys64 { unsigned int a[TT]; unsigned int b[TT]; };

__device__ __forceinline__ float u01(unsigned int bits) {
    return __uint_as_float((bits >> 9) | 0x3f800000u) - 1.0f;
}
__device__ __forceinline__ float sigmoidf_(float x) {
    return 1.0f / (1.0f + expf(-x));
}

// ---------------- SGEMM v2: 128x128x16, double-buffered, 8x8 microtile ------
// C[M,N] = A * B.  TA=false: A row-major [M,K]. TA=true: compute with A^T
// where A is stored row-major [K,M].  B row-major [K,N].
// Requires M%128==0, N%128==0, K%16==0.
template<bool TA>
__global__ void __launch_bounds__(256)
sgemm2(const float* __restrict__ A, const float* __restrict__ B,
       float* __restrict__ C, int M, int N, int K)
{
    __shared__ float As[2][16][128];
    __shared__ float Bs[2][16][128];

    const int tid = threadIdx.x;
    const int m0 = blockIdx.y * 128;
    const int n0 = blockIdx.x * 128;
    const int tx = tid & 15;   // n dir
    const int ty = tid >> 4;   // m dir

    float acc[8][8];
#pragma unroll
    for (int i = 0; i < 8; i++)
#pragma unroll
        for (int j = 0; j < 8; j++) acc[i][j] = 0.0f;

    const int nt = K / 16;
    float4 ra0, ra1, rb0, rb1;

    auto ldg = [&](int kt) {
        if (!TA) {
            const int f0 = tid * 2, f1 = f0 + 1;
            ra0 = *(const float4*)&A[(long)(m0 + (f0 >> 2)) * K + kt * 16 + (f0 & 3) * 4];
            ra1 = *(const float4*)&A[(long)(m0 + (f1 >> 2)) * K + kt * 16 + (f1 & 3) * 4];
        } else {
            ra0 = *(const float4*)&A[(long)(kt * 16 + (tid >> 5)) * M + m0 + (tid & 31) * 4];
            ra1 = *(const float4*)&A[(long)(kt * 16 + (tid >> 5) + 8) * M + m0 + (tid & 31) * 4];
        }
        rb0 = *(const float4*)&B[(long)(kt * 16 + (tid >> 5)) * N + n0 + (tid & 31) * 4];
        rb1 = *(const float4*)&B[(long)(kt * 16 + (tid >> 5) + 8) * N + n0 + (tid & 31) * 4];
    };
    auto sts = [&](int buf) {
        if (!TA) {
            const int f0 = tid * 2, f1 = f0 + 1;
            const int r0 = f0 >> 2, c0 = (f0 & 3) * 4;
            As[buf][c0 + 0][r0] = ra0.x; As[buf][c0 + 1][r0] = ra0.y;
            As[buf][c0 + 2][r0] = ra0.z; As[buf][c0 + 3][r0] = ra0.w;
            const int r1 = f1 >> 2, c1 = (f1 & 3) * 4;
            As[buf][c1 + 0][r1] = ra1.x; As[buf][c1 + 1][r1] = ra1.y;
            As[buf][c1 + 2][r1] = ra1.z; As[buf][c1 + 3][r1] = ra1.w;
        } else {
            *(float4*)&As[buf][tid >> 5][(tid & 31) * 4]       = ra0;
            *(float4*)&As[buf][(tid >> 5) + 8][(tid & 31) * 4] = ra1;
        }
        *(float4*)&Bs[buf][tid >> 5][(tid & 31) * 4]       = rb0;
        *(float4*)&Bs[buf][(tid >> 5) + 8][(tid & 31) * 4] = rb1;
    };

    ldg(0); sts(0); __syncthreads();

    for (int kt = 0; kt < nt; kt++) {
        const int cur = kt & 1;
        if (kt + 1 < nt) ldg(kt + 1);
#pragma unroll
        for (int kk = 0; kk < 16; kk++) {
            float4 a0 = *(const float4*)&As[cur][kk][ty * 8];
            float4 a1 = *(const float4*)&As[cur][kk][ty * 8 + 4];
            float4 b0 = *(const float4*)&Bs[cur][kk][tx * 8];
            float4 b1 = *(const float4*)&Bs[cur][kk][tx * 8 + 4];
            float av[8] = {a0.x, a0.y, a0.z, a0.w, a1.x, a1.y, a1.z, a1.w};
            float bv[8] = {b0.x, b0.y, b0.z, b0.w, b1.x, b1.y, b1.z, b1.w};
#pragma unroll
            for (int i = 0; i < 8; i++)
#pragma unroll
                for (int j = 0; j < 8; j++)
                    acc[i][j] = fmaf(av[i], bv[j], acc[i][j]);
        }
        if (kt + 1 < nt) { sts(cur ^ 1); __syncthreads(); }
    }

#pragma unroll
    for (int i = 0; i < 8; i++) {
        long row = (long)(m0 + ty * 8 + i) * N + n0 + tx * 8;
        *(float4*)&C[row]     = make_float4(acc[i][0], acc[i][1], acc[i][2], acc[i][3]);
        *(float4*)&C[row + 4] = make_float4(acc[i][4], acc[i][5], acc[i][6], acc[i][7]);
    }
}

// ---------------- recurrence ------------------------------------------------
// t = 0: hb = b_init, rt = sigmoid(hb + WV)
__global__ void __launch_bounds__(256)
recur_init(const float* __restrict__ b_init, const float* __restrict__ WV,
           float* __restrict__ rt, float* __restrict__ hb)
{
    int tidx = blockIdx.x * blockDim.x + threadIdx.x;  // 0..32767
    int i = tidx >> 5, b = tidx & 31;
    long idx = (long)i * TBB + b;
    float acc = b_init[i];
    hb[idx] = acc;
    rt[idx] = sigmoidf_(acc + WV[idx]);
}

// t >= 1: hb = b_h + U @ r_{t-1};  rt = sigmoid(hb + WV[:,t,:])
// Block: 4 rows of U staged in smem; 8 warps = 8 K-chunks; lane = batch col.
__global__ void __launch_bounds__(256)
recur_v2(const float* __restrict__ U, const float* __restrict__ b_h,
         const float* __restrict__ WV, float* __restrict__ rt,
         float* __restrict__ hb, int t)
{
    __shared__ float Us[4][NHH];
    __shared__ float part[8][4][32];

    const int tid = threadIdx.x;
    const int i0 = blockIdx.x * 4;

    // stage 4 rows of U (16 KB), coalesced float4
#pragma unroll
    for (int q = 0; q < 4; q++) {
        int f = tid + q * 256;           // float4 index 0..1023
        int r = f >> 8, c = f & 255;
        *(float4*)&Us[r][c * 4] = *(const float4*)&U[(long)(i0 + r) * NHH + c * 4];
    }
    __syncthreads();

    const int jq = tid >> 5;   // K-chunk (warp)
    const int b  = tid & 31;   // batch lane
    const float* __restrict__ rprev = rt + (long)(t - 1) * BBB + b;

    float a0 = 0.f, a1 = 0.f, a2 = 0.f, a3 = 0.f;
    const int j0 = jq * 128;
#pragma unroll 4
    for (int j = j0; j < j0 + 128; j++) {
        float rv = __ldg(&rprev[(long)j * TBB]);
        a0 = fmaf(Us[0][j], rv, a0);
        a1 = fmaf(Us[1][j], rv, a1);
        a2 = fmaf(Us[2][j], rv, a2);
        a3 = fmaf(Us[3][j], rv, a3);
    }
    part[jq][0][b] = a0; part[jq][1][b] = a1;
    part[jq][2][b] = a2; part[jq][3][b] = a3;
    __syncthreads();

    if (tid < 128) {
        const int r = tid >> 5, bb = tid & 31;
        float s = 0.f;
#pragma unroll
        for (int q = 0; q < 8; q++) s += part[q][r][bb];   // fixed order: deterministic
        const int i = i0 + r;
        long idx = (long)i * TBB + (long)t * BBB + bb;
        float acc = b_h[i] + s;
        hb[idx] = acc;
        rt[idx] = sigmoidf_(acc + WV[idx]);
    }
}

// ---------------- bernoulli sampling ----------------------------------------
// JAX threefry_partitionable=True:
//   bits at flat index n -> threefry2x32(key, (0, n)); word = lane1 ^ lane2.
__global__ void __launch_bounds__(256)
sample_kernel(const float* __restrict__ pre,
              const float* __restrict__ rowbias,   // b_v or nullptr
              const float* __restrict__ fullbias,  // hid_bias or nullptr
              float* __restrict__ outbuf,
              Keys64 keys, int N, int preIsProb)
{
    const int t = blockIdx.y;
    const int n = blockIdx.x * blockDim.x + threadIdx.x;  // 0 .. N*B-1

    unsigned int b1, b2;
    tf2x32(keys.a[t], keys.b[t], 0u, (unsigned int)n, b1, b2);
    float uu = u01(b1 ^ b2);

    const int i = n >> 5;
    const int b = n & 31;
    const long idx = (long)i * TBB + (long)t * BBB + b;

    float p;
    if (preIsProb) {
        p = pre[idx];
    } else {
        float x = pre[idx];
        if (rowbias)  x += rowbias[i];
        if (fullbias) x += fullbias[idx];
        p = sigmoidf_(x);
    }
    outbuf[idx] = (uu < p) ? 1.0f : 0.0f;
}

// ---------------- host ------------------------------------------------------
extern "C" void kernel_launch(void* const* d_in, const int* in_sizes, int n_in,
                              void* d_out, int out_size)
{
    const float* v      = (const float*)d_in[0];  // [NV, T, B]
    const float* W      = (const float*)d_in[1];  // [NH, NV]
    const float* U      = (const float*)d_in[2];  // [NH, NH]
    const float* b_v    = (const float*)d_in[3];  // [NV]
    const float* b_h    = (const float*)d_in[4];  // [NH]
    const float* b_init = (const float*)d_in[5];  // [NH]

    float* out    = (float*)d_out;
    float* vmodel = out;                                   // [NV, T, B]
    float* rmodel = out + (long)NVV * TBB;                 // [NH, T, B]
    float* rt     = out + (long)(NVV + NHH) * TBB;         // [NH, T, B]

    float *WV, *HB, *H1, *P, *VM, *Q, *R;
    cudaGetSymbolAddress((void**)&WV, g_WV);
    cudaGetSymbolAddress((void**)&HB, g_HB);
    cudaGetSymbolAddress((void**)&H1, g_H1);
    cudaGetSymbolAddress((void**)&P,  g_P);
    cudaGetSymbolAddress((void**)&VM, g_VM);
    cudaGetSymbolAddress((void**)&Q,  g_Q);
    cudaGetSymbolAddress((void**)&R,  g_R);

    // ---- JAX key schedule, threefry_partitionable=True ----------------------
    unsigned int tk0[TT], tk1[TT];
    unsigned int ksa, ksb;
    tf2x32(0u, 42u, 0u, 0u, tk0[0], tk1[0]);   // k0
    tf2x32(0u, 42u, 0u, 1u, ksa, ksb);         // ks
    for (int t = 1; t < TT; t++)
        tf2x32(ksa, ksb, 0u, (unsigned int)(t - 1), tk0[t], tk1[t]);

    Keys64 KH1, KVM, KH2, KVX;
    for (int t = 0; t < TT; t++) {
        tf2x32(tk0[t], tk1[t], 0u, 0u, KH1.a[t], KH1.b[t]);
        tf2x32(tk0[t], tk1[t], 0u, 1u, KVM.a[t], KVM.b[t]);
        tf2x32(tk0[t], tk1[t], 0u, 2u, KH2.a[t], KH2.b[t]);
        tf2x32(tk0[t], tk1[t], 0u, 3u, KVX.a[t], KVX.b[t]);
    }

    // ---- pipeline -----------------------------------------------------------
    // 1) WV = W @ V        [1024 x 2048], K=4096
    sgemm2<false><<<dim3(TBB / 128, NHH / 128), 256>>>(W, v, WV, NHH, TBB, NVV);

    // 2) sequential recurrence over t
    recur_init<<<(NHH * BBB) / 256, 256>>>(b_init, WV, rt, HB);
    for (int t = 1; t < TT; t++)
        recur_v2<<<NHH / 4, 256>>>(U, b_h, WV, rt, HB, t);

    // 3) h1 = bern(rt)
    sample_kernel<<<dim3((NHH * BBB) / 256, TT), 256>>>(
        rt, nullptr, nullptr, H1, KH1, NHH, 1);

    // 4) P = W^T @ H1      [4096 x 2048], K=1024
    sgemm2<true><<<dim3(TBB / 128, NVV / 128), 256>>>(W, H1, P, NVV, TBB, NHH);

    // 5) vm = bern(sigmoid(P + b_v))
    sample_kernel<<<dim3((NVV * BBB) / 256, TT), 256>>>(
        P, b_v, nullptr, VM, KVM, NVV, 0);

    // 6) Q = W @ VM        [1024 x 2048], K=4096
    sgemm2<false><<<dim3(TBB / 128, NHH / 128), 256>>>(W, VM, Q, NHH, TBB, NVV);

    // 7) h2 = bern(sigmoid(Q + hid_bias))  -> r_model output (also H2 input)
    sample_kernel<<<dim3((NHH * BBB) / 256, TT), 256>>>(
        Q, nullptr, HB, rmodel, KH2, NHH, 0);

    // 8) R = W^T @ H2      [4096 x 2048], K=1024
    sgemm2<true><<<dim3(TBB / 128, NVV / 128), 256>>>(W, rmodel, R, NVV, TBB, NHH);

    // 9) v_model = bern(sigmoid(R + b_v))
    sample_kernel<<<dim3((NVV * BBB) / 256, TT), 256>>>(
        R, b_v, nullptr, vmodel, KVX, NVV, 0);

    (void)in_sizes; (void)n_in; (void)out_size;
}

// round 7
// speedup vs baseline: 1.8146x; 1.0046x over previous
#include <cuda_runtime.h>
#include <cuda_bf16.h>

#define NVV 4096
#define NHH 1024
#define TT  64
#define BBB 32
#define TBB 2048   // T*B
#define RGRID 128  // persistent recurrence grid (must be <= SM count)

// ---------------- scratch (static device globals; no allocation) -----------
__device__ float g_WV[NHH * TBB];   // W @ V            [NH, T*B]
__device__ float g_HB[NHH * TBB];   // hid_bias         [NH, T*B]
__device__ float g_H1[NHH * TBB];   // first h sample   [NH, T*B]
__device__ float g_P [NVV * TBB];   // W^T @ H1         [NV, T*B]
__device__ float g_VM[NVV * TBB];   // vm sample        [NV, T*B]
__device__ float g_Q [NHH * TBB];   // W @ VM           [NH, T*B]
__device__ float g_R [NVV * TBB];   // W^T @ H2         [NV, T*B]
__device__ unsigned int g_step_count[TT];   // per-step grid-barrier arrivals

// ---------------- threefry2x32 (JAX-compatible) -----------------------------
__host__ __device__ __forceinline__ unsigned int rotl32(unsigned int v, int d) {
    return (v << d) | (v >> (32 - d));
}

__host__ __device__ inline void tf2x32(unsigned int k0, unsigned int k1,
                                       unsigned int x0, unsigned int x1,
                                       unsigned int &o0, unsigned int &o1)
{
    unsigned int ks2 = k0 ^ k1 ^ 0x1BD11BDAu;
    x0 += k0; x1 += k1;
#define TF_R(r) { x0 += x1; x1 = rotl32(x1, (r)); x1 ^= x0; }
    TF_R(13) TF_R(15) TF_R(26) TF_R(6)
    x0 += k1;  x1 += ks2 + 1u;
    TF_R(17) TF_R(29) TF_R(16) TF_R(24)
    x0 += ks2; x1 += k0 + 2u;
    TF_R(13) TF_R(15) TF_R(26) TF_R(6)
    x0 += k0;  x1 += k1 + 3u;
    TF_R(17) TF_R(29) TF_R(16) TF_R(24)
    x0 += k1;  x1 += ks2 + 4u;
    TF_R(13) TF_R(15) TF_R(26) TF_R(6)
    x0 += ks2; x1 += k0 + 5u;
#undef TF_R
    o0 = x0; o1 = x1;
}

struct Keys64 { unsigned int a[TT]; unsigned int b[TT]; };

__device__ __forceinline__ float u01(unsigned int bits) {
    return __uint_as_float((bits >> 9) | 0x3f800000u) - 1.0f;
}
__device__ __forceinline__ float sigmoidf_(float x) {
    return 1.0f / (1.0f + expf(-x));
}

// ---------------- SGEMM v2: 128x128x16, double-buffered, 8x8 microtile ------
template<bool TA>
__global__ void __launch_bounds__(256)
sgemm2(const float* __restrict__ A, const float* __restrict__ B,
       float* __restrict__ C, int M, int N, int K)
{
    __shared__ float As[2][16][128];
    __shared__ float Bs[2][16][128];

    const int tid = threadIdx.x;
    const int m0 = blockIdx.y * 128;
    const int n0 = blockIdx.x * 128;
    const int tx = tid & 15;   // n dir
    const int ty = tid >> 4;   // m dir

    float acc[8][8];
#pragma unroll
    for (int i = 0; i < 8; i++)
#pragma unroll
        for (int j = 0; j < 8; j++) acc[i][j] = 0.0f;

    const int nt = K / 16;
    float4 ra0, ra1, rb0, rb1;

    auto ldg = [&](int kt) {
        if (!TA) {
            const int f0 = tid * 2, f1 = f0 + 1;
            ra0 = *(const float4*)&A[(long)(m0 + (f0 >> 2)) * K + kt * 16 + (f0 & 3) * 4];
            ra1 = *(const float4*)&A[(long)(m0 + (f1 >> 2)) * K + kt * 16 + (f1 & 3) * 4];
        } else {
            ra0 = *(const float4*)&A[(long)(kt * 16 + (tid >> 5)) * M + m0 + (tid & 31) * 4];
            ra1 = *(const float4*)&A[(long)(kt * 16 + (tid >> 5) + 8) * M + m0 + (tid & 31) * 4];
        }
        rb0 = *(const float4*)&B[(long)(kt * 16 + (tid >> 5)) * N + n0 + (tid & 31) * 4];
        rb1 = *(const float4*)&B[(long)(kt * 16 + (tid >> 5) + 8) * N + n0 + (tid & 31) * 4];
    };
    auto sts = [&](int buf) {
        if (!TA) {
            const int f0 = tid * 2, f1 = f0 + 1;
            const int r0 = f0 >> 2, c0 = (f0 & 3) * 4;
            As[buf][c0 + 0][r0] = ra0.x; As[buf][c0 + 1][r0] = ra0.y;
            As[buf][c0 + 2][r0] = ra0.z; As[buf][c0 + 3][r0] = ra0.w;
            const int r1 = f1 >> 2, c1 = (f1 & 3) * 4;
            As[buf][c1 + 0][r1] = ra1.x; As[buf][c1 + 1][r1] = ra1.y;
            As[buf][c1 + 2][r1] = ra1.z; As[buf][c1 + 3][r1] = ra1.w;
        } else {
            *(float4*)&As[buf][tid >> 5][(tid & 31) * 4]       = ra0;
            *(float4*)&As[buf][(tid >> 5) + 8][(tid & 31) * 4] = ra1;
        }
        *(float4*)&Bs[buf][tid >> 5][(tid & 31) * 4]       = rb0;
        *(float4*)&Bs[buf][(tid >> 5) + 8][(tid & 31) * 4] = rb1;
    };

    ldg(0); sts(0); __syncthreads();

    for (int kt = 0; kt < nt; kt++) {
        const int cur = kt & 1;
        if (kt + 1 < nt) ldg(kt + 1);
#pragma unroll
        for (int kk = 0; kk < 16; kk++) {
            float4 a0 = *(const float4*)&As[cur][kk][ty * 8];
            float4 a1 = *(const float4*)&As[cur][kk][ty * 8 + 4];
            float4 b0 = *(const float4*)&Bs[cur][kk][tx * 8];
            float4 b1 = *(const float4*)&Bs[cur][kk][tx * 8 + 4];
            float av[8] = {a0.x, a0.y, a0.z, a0.w, a1.x, a1.y, a1.z, a1.w};
            float bv[8] = {b0.x, b0.y, b0.z, b0.w, b1.x, b1.y, b1.z, b1.w};
#pragma unroll
            for (int i = 0; i < 8; i++)
#pragma unroll
                for (int j = 0; j < 8; j++)
                    acc[i][j] = fmaf(av[i], bv[j], acc[i][j]);
        }
        if (kt + 1 < nt) { sts(cur ^ 1); __syncthreads(); }
    }

#pragma unroll
    for (int i = 0; i < 8; i++) {
        long row = (long)(m0 + ty * 8 + i) * N + n0 + tx * 8;
        *(float4*)&C[row]     = make_float4(acc[i][0], acc[i][1], acc[i][2], acc[i][3]);
        *(float4*)&C[row + 4] = make_float4(acc[i][4], acc[i][5], acc[i][6], acc[i][7]);
    }
}

// ---------------- recurrence ------------------------------------------------
// t = 0: hb = b_init, rt = sigmoid(hb + WV)
__global__ void __launch_bounds__(256)
recur_init(const float* __restrict__ b_init, const float* __restrict__ WV,
           float* __restrict__ rt, float* __restrict__ hb)
{
    int tidx = blockIdx.x * blockDim.x + threadIdx.x;  // 0..32767
    int i = tidx >> 5, b = tidx & 31;
    long idx = (long)i * TBB + b;
    float acc = b_init[i];
    hb[idx] = acc;
    rt[idx] = sigmoidf_(acc + WV[idx]);
}

// Persistent recurrence: one launch covers t = 1..63.
// 128 blocks x 256 threads, all co-resident. Each block owns 8 rows of U
// (staged in smem once). Per step: 8 warps = 8 K-chunks of 128; lane = batch.
// Device-wide sync between steps via per-step monotonic arrival counters.
__global__ void __launch_bounds__(256)
recur_persist(const float* __restrict__ U, const float* __restrict__ b_h,
              const float* __restrict__ WV, float* __restrict__ rt,
              float* __restrict__ hb)
{
    __shared__ float Us[8][NHH];        // 32 KB
    __shared__ float part[8][8][32];    // [warp][row][batch], 8 KB

    const int tid = threadIdx.x;
    const int i0 = blockIdx.x * 8;

    // stage 8 rows of U once (2048 float4 over 256 threads)
#pragma unroll
    for (int q = 0; q < 8; q++) {
        int f = tid + q * 256;          // float4 index 0..2047
        int r = f >> 8, c = f & 255;
        *(float4*)&Us[r][c * 4] = *(const float4*)&U[(long)(i0 + r) * NHH + c * 4];
    }
    __syncthreads();

    const int w = tid >> 5;   // warp = K-chunk
    const int b = tid & 31;   // batch lane
    const int j0 = w * 128;
    const int rr = tid >> 5, bb = tid & 31;   // reduction role (8 rows x 32)
    const float bh = b_h[i0 + rr];

    for (int t = 1; t < TT; t++) {
        const float* __restrict__ rprev = rt + (long)(t - 1) * BBB + b;

        float acc[8];
#pragma unroll
        for (int r = 0; r < 8; r++) acc[r] = 0.0f;

#pragma unroll 2
        for (int jj = j0; jj < j0 + 128; jj += 4) {
            float rv0 = __ldg(&rprev[(long)(jj + 0) * TBB]);
            float rv1 = __ldg(&rprev[(long)(jj + 1) * TBB]);
            float rv2 = __ldg(&rprev[(long)(jj + 2) * TBB]);
            float rv3 = __ldg(&rprev[(long)(jj + 3) * TBB]);
#pragma unroll
            for (int r = 0; r < 8; r++) {
                float4 u = *(const float4*)&Us[r][jj];
                acc[r] = fmaf(u.x, rv0, acc[r]);
                acc[r] = fmaf(u.y, rv1, acc[r]);
                acc[r] = fmaf(u.z, rv2, acc[r]);
                acc[r] = fmaf(u.w, rv3, acc[r]);
            }
        }
#pragma unroll
        for (int r = 0; r < 8; r++) part[w][r][b] = acc[r];
        __syncthreads();

        // reduce 8 warp-partials in fixed order (deterministic), write outputs
        {
            float s = 0.0f;
#pragma unroll
            for (int q = 0; q < 8; q++) s += part[q][rr][bb];
            const long idx = (long)(i0 + rr) * TBB + (long)t * BBB + bb;
            float a = bh + s;
            hb[idx] = a;
            rt[idx] = sigmoidf_(a + WV[idx]);
        }
        __syncthreads();   // all writes done; part safe to reuse next iter

        // device-wide barrier (per-step monotonic counter; no reset needed)
        if (tid == 0) {
            __threadfence();
            atomicAdd(&g_step_count[t], 1u);
            volatile unsigned int* p = &g_step_count[t];
            while (*p < (unsigned int)gridDim.x) { }
            __threadfence();
        }
        __syncthreads();
    }
}

// ---------------- bernoulli sampling ----------------------------------------
// JAX threefry_partitionable=True:
//   bits at flat index n -> threefry2x32(key, (0, n)); word = lane1 ^ lane2.
__global__ void __launch_bounds__(256)
sample_kernel(const float* __restrict__ pre,
              const float* __restrict__ rowbias,   // b_v or nullptr
              const float* __restrict__ fullbias,  // hid_bias or nullptr
              float* __restrict__ outbuf,
              Keys64 keys, int N, int preIsProb)
{
    const int t = blockIdx.y;
    const int n = blockIdx.x * blockDim.x + threadIdx.x;  // 0 .. N*B-1

    unsigned int b1, b2;
    tf2x32(keys.a[t], keys.b[t], 0u, (unsigned int)n, b1, b2);
    float uu = u01(b1 ^ b2);

    const int i = n >> 5;
    const int b = n & 31;
    const long idx = (long)i * TBB + (long)t * BBB + b;

    float p;
    if (preIsProb) {
        p = pre[idx];
    } else {
        float x = pre[idx];
        if (rowbias)  x += rowbias[i];
        if (fullbias) x += fullbias[idx];
        p = sigmoidf_(x);
    }
    outbuf[idx] = (uu < p) ? 1.0f : 0.0f;
}

// ---------------- host ------------------------------------------------------
extern "C" void kernel_launch(void* const* d_in, const int* in_sizes, int n_in,
                              void* d_out, int out_size)
{
    const float* v      = (const float*)d_in[0];  // [NV, T, B]
    const float* W      = (const float*)d_in[1];  // [NH, NV]
    const float* U      = (const float*)d_in[2];  // [NH, NH]
    const float* b_v    = (const float*)d_in[3];  // [NV]
    const float* b_h    = (const float*)d_in[4];  // [NH]
    const float* b_init = (const float*)d_in[5];  // [NH]

    float* out    = (float*)d_out;
    float* vmodel = out;                                   // [NV, T, B]
    float* rmodel = out + (long)NVV * TBB;                 // [NH, T, B]
    float* rt     = out + (long)(NVV + NHH) * TBB;         // [NH, T, B]

    float *WV, *HB, *H1, *P, *VM, *Q, *R;
    cudaGetSymbolAddress((void**)&WV, g_WV);
    cudaGetSymbolAddress((void**)&HB, g_HB);
    cudaGetSymbolAddress((void**)&H1, g_H1);
    cudaGetSymbolAddress((void**)&P,  g_P);
    cudaGetSymbolAddress((void**)&VM, g_VM);
    cudaGetSymbolAddress((void**)&Q,  g_Q);
    cudaGetSymbolAddress((void**)&R,  g_R);

    void* bar;
    cudaGetSymbolAddress(&bar, g_step_count);
    cudaMemsetAsync(bar, 0, TT * sizeof(unsigned int));   // replay-safe reset

    // ---- JAX key schedule, threefry_partitionable=True ----------------------
    unsigned int tk0[TT], tk1[TT];
    unsigned int ksa, ksb;
    tf2x32(0u, 42u, 0u, 0u, tk0[0], tk1[0]);   // k0
    tf2x32(0u, 42u, 0u, 1u, ksa, ksb);         // ks
    for (int t = 1; t < TT; t++)
        tf2x32(ksa, ksb, 0u, (unsigned int)(t - 1), tk0[t], tk1[t]);

    Keys64 KH1, KVM, KH2, KVX;
    for (int t = 0; t < TT; t++) {
        tf2x32(tk0[t], tk1[t], 0u, 0u, KH1.a[t], KH1.b[t]);
        tf2x32(tk0[t], tk1[t], 0u, 1u, KVM.a[t], KVM.b[t]);
        tf2x32(tk0[t], tk1[t], 0u, 2u, KH2.a[t], KH2.b[t]);
        tf2x32(tk0[t], tk1[t], 0u, 3u, KVX.a[t], KVX.b[t]);
    }

    // ---- pipeline -----------------------------------------------------------
    // 1) WV = W @ V        [1024 x 2048], K=4096
    sgemm2<false><<<dim3(TBB / 128, NHH / 128), 256>>>(W, v, WV, NHH, TBB, NVV);

    // 2) recurrence: t=0 init, then persistent kernel for t=1..63
    recur_init<<<(NHH * BBB) / 256, 256>>>(b_init, WV, rt, HB);
    recur_persist<<<RGRID, 256>>>(U, b_h, WV, rt, HB);

    // 3) h1 = bern(rt)
    sample_kernel<<<dim3((NHH * BBB) / 256, TT), 256>>>(
        rt, nullptr, nullptr, H1, KH1, NHH, 1);

    // 4) P = W^T @ H1      [4096 x 2048], K=1024
    sgemm2<true><<<dim3(TBB / 128, NVV / 128), 256>>>(W, H1, P, NVV, TBB, NHH);

    // 5) vm = bern(sigmoid(P + b_v))
    sample_kernel<<<dim3((NVV * BBB) / 256, TT), 256>>>(
        P, b_v, nullptr, VM, KVM, NVV, 0);

    // 6) Q = W @ VM        [1024 x 2048], K=4096
    sgemm2<false><<<dim3(TBB / 128, NHH / 128), 256>>>(W, VM, Q, NHH, TBB, NVV);

    // 7) h2 = bern(sigmoid(Q + hid_bias))  -> r_model output (also H2 input)
    sample_kernel<<<dim3((NHH * BBB) / 256, TT), 256>>>(
        Q, nullptr, HB, rmodel, KH2, NHH, 0);

    // 8) R = W^T @ H2      [4096 x 2048], K=1024
    sgemm2<true><<<dim3(TBB / 128, NVV / 128), 256>>>(W, rmodel, R, NVV, TBB, NHH);

    // 9) v_model = bern(sigmoid(R + b_v))
    sample_kernel<<<dim3((NVV * BBB) / 256, TT), 256>>>(
        R, b_v, nullptr, vmodel, KVX, NVV, 0);

    (void)in_sizes; (void)n_in; (void)out_size;
}